// round 1
// baseline (speedup 1.0000x reference)
#include <cuda_runtime.h>
#include <math.h>

#define K_CODES 1024
#define C_DIM   64
#define N_TOT   32768
#define TILE_N  128
#define TILE_K  128
#define N_BLOCKS (N_TOT / TILE_N)   // 256

#define Q_ELEMS  (32*64*32*32)      // 2097152
#define LOSS_OFF Q_ELEMS
#define IDX_OFF  (Q_ELEMS + 1)
#define PERP_OFF (Q_ELEMS + 1 + N_TOT)

// scratch (no allocations allowed -> device globals)
__device__ float g_enrm[K_CODES];
__device__ int   g_counts[K_CODES];
__device__ float g_loss_partial[N_BLOCKS];

// ---------------------------------------------------------------------------
// Prep: ||e_k||^2 per code, zero counts (must run every launch: graph replay)
// ---------------------------------------------------------------------------
__global__ void vq_prep(const float* __restrict__ embed) {
    int k = blockIdx.x * blockDim.x + threadIdx.x;   // 0..1023
    float s = 0.f;
#pragma unroll
    for (int c = 0; c < C_DIM; ++c) {
        float e = embed[c * K_CODES + k];
        s += e * e;
    }
    g_enrm[k]   = s;
    g_counts[k] = 0;
}

// ---------------------------------------------------------------------------
// Main: fused distance-GEMM + argmin + gather + quantized write + loss partial
// Block = 128 vectors (one b, contiguous hw). 256 threads = 16(tx,k) x 16(ty,n),
// 8x8 register micro-tile. K tiled by 128 through shared memory.
// ---------------------------------------------------------------------------
__global__ __launch_bounds__(256) void vq_main(const float* __restrict__ inputs,
                                               const float* __restrict__ embed,
                                               float* __restrict__ out)
{
    extern __shared__ float smem[];
    float* sx    = smem;                       // [C_DIM][TILE_N]  32KB
    float* se    = sx + C_DIM * TILE_N;        // [C_DIM][TILE_K]  32KB
    float* senrm = se + C_DIM * TILE_K;        // [TILE_K]
    int*   sidx  = (int*)(senrm + TILE_K);     // [TILE_N]
    float* sred  = (float*)(sidx + TILE_N);    // [8]

    const int tid    = threadIdx.x;
    const int tx     = tid & 15;               // k micro-tile lane
    const int ty     = tid >> 4;               // n micro-tile lane
    const int base_n = blockIdx.x * TILE_N;
    const int b      = base_n >> 10;           // 128 | 1024, tile stays in one b
    const int hw0    = base_n & 1023;

    // Load x tile: sx[c][nl] = inputs[b, c, hw0+nl]  (coalesced over nl)
    for (int idx = tid; idx < C_DIM * TILE_N; idx += 256) {
        int c = idx >> 7, nl = idx & 127;
        sx[idx] = inputs[b * 65536 + c * 1024 + hw0 + nl];
    }

    float mind[8];
    int   mini[8];
#pragma unroll
    for (int i = 0; i < 8; ++i) { mind[i] = 3.4e38f; mini[i] = 0; }

    for (int k0 = 0; k0 < K_CODES; k0 += TILE_K) {
        __syncthreads();   // protect se/senrm from previous iteration's readers
        for (int idx = tid; idx < C_DIM * TILE_K; idx += 256) {
            int c = idx >> 7, kk = idx & 127;
            se[idx] = embed[c * 1024 + k0 + kk];
        }
        if (tid < TILE_K) senrm[tid] = g_enrm[k0 + tid];
        __syncthreads();

        float acc[8][8];
#pragma unroll
        for (int i = 0; i < 8; ++i)
#pragma unroll
            for (int j = 0; j < 8; ++j) acc[i][j] = 0.f;

        const float* sxp = sx + ty * 8;
        const float* sep = se + tx * 8;
#pragma unroll 4
        for (int c = 0; c < C_DIM; ++c) {
            float4 x0 = *(const float4*)(sxp + c * TILE_N);
            float4 x1 = *(const float4*)(sxp + c * TILE_N + 4);
            float4 e0 = *(const float4*)(sep + c * TILE_K);
            float4 e1 = *(const float4*)(sep + c * TILE_K + 4);
            float xv[8] = {x0.x, x0.y, x0.z, x0.w, x1.x, x1.y, x1.z, x1.w};
            float ev[8] = {e0.x, e0.y, e0.z, e0.w, e1.x, e1.y, e1.z, e1.w};
#pragma unroll
            for (int i = 0; i < 8; ++i)
#pragma unroll
                for (int j = 0; j < 8; ++j) acc[i][j] += xv[i] * ev[j];
        }

        // argmin update: d = ||e||^2 - 2 x.e  (||x||^2 constant -> dropped)
        float en[8];
#pragma unroll
        for (int j = 0; j < 8; ++j) en[j] = senrm[tx * 8 + j];
#pragma unroll
        for (int i = 0; i < 8; ++i) {
#pragma unroll
            for (int j = 0; j < 8; ++j) {
                float d = en[j] - 2.f * acc[i][j];
                if (d < mind[i]) { mind[i] = d; mini[i] = k0 + tx * 8 + j; }
            }
        }
    }

    // Reduce across the 16 tx lanes (half-warp butterflies; ascending-k order
    // was preserved per-thread, tie-break picks the smaller index like argmin).
#pragma unroll
    for (int i = 0; i < 8; ++i) {
#pragma unroll
        for (int m = 1; m < 16; m <<= 1) {
            float od = __shfl_xor_sync(0xFFFFFFFFu, mind[i], m);
            int   oi = __shfl_xor_sync(0xFFFFFFFFu, mini[i], m);
            if (od < mind[i] || (od == mind[i] && oi < mini[i])) {
                mind[i] = od; mini[i] = oi;
            }
        }
    }

    if (tx == 0) {
#pragma unroll
        for (int i = 0; i < 8; ++i) {
            int nl = ty * 8 + i;
            sidx[nl] = mini[i];
            out[IDX_OFF + base_n + nl] = (float)mini[i];
            atomicAdd(&g_counts[mini[i]], 1);   // int atomics: deterministic
        }
    }
    __syncthreads();

    // Epilogue: gather quantized, write (B,C,H,W) coalesced over hw, loss partial
    float lsum = 0.f;
    for (int idx = tid; idx < C_DIM * TILE_N; idx += 256) {
        int c = idx >> 7, nl = idx & 127;
        int kq = sidx[nl];
        float q = __ldg(&embed[c * 1024 + kq]);   // embed resident in L2
        float x = sx[idx];
        out[b * 65536 + c * 1024 + hw0 + nl] = q;
        float dv = q - x;
        lsum += dv * dv;
    }
    // deterministic block reduction of loss partial
#pragma unroll
    for (int m = 16; m > 0; m >>= 1) lsum += __shfl_xor_sync(0xFFFFFFFFu, lsum, m);
    if ((tid & 31) == 0) sred[tid >> 5] = lsum;
    __syncthreads();
    if (tid == 0) {
        float s = 0.f;
#pragma unroll
        for (int w = 0; w < 8; ++w) s += sred[w];
        g_loss_partial[blockIdx.x] = s;
    }
}

// ---------------------------------------------------------------------------
// Finalize: perplexity from counts, loss from partials (fixed-order trees)
// ---------------------------------------------------------------------------
__global__ void vq_finalize(float* __restrict__ out) {
    __shared__ float sh[1024];
    int t = threadIdx.x;

    float p = (float)g_counts[t] * (1.f / 32768.f);
    sh[t] = p * logf(p + 1e-10f);
    __syncthreads();
    for (int s = 512; s > 0; s >>= 1) {
        if (t < s) sh[t] += sh[t + s];
        __syncthreads();
    }
    if (t == 0) out[PERP_OFF] = expf(-sh[0]);
    __syncthreads();

    sh[t] = (t < N_BLOCKS) ? g_loss_partial[t] : 0.f;
    __syncthreads();
    for (int s = 512; s > 0; s >>= 1) {
        if (t < s) sh[t] += sh[t + s];
        __syncthreads();
    }
    if (t == 0) out[LOSS_OFF] = 0.25f * sh[0] / (float)Q_ELEMS;
}

// ---------------------------------------------------------------------------
extern "C" void kernel_launch(void* const* d_in, const int* in_sizes, int n_in,
                              void* d_out, int out_size) {
    const float* inputs = (const float*)d_in[0];
    const float* embed  = (const float*)d_in[1];
    // robustness: identify by size in case of input-order surprise
    if (n_in >= 2 && in_sizes[0] == K_CODES * C_DIM && in_sizes[1] == Q_ELEMS) {
        const float* t = inputs; inputs = embed; embed = t;
    }
    float* out = (float*)d_out;

    const size_t smem_bytes =
        (size_t)(C_DIM * TILE_N + C_DIM * TILE_K + TILE_K) * sizeof(float)
        + TILE_N * sizeof(int) + 64 * sizeof(float);
    cudaFuncSetAttribute(vq_main, cudaFuncAttributeMaxDynamicSharedMemorySize,
                         (int)smem_bytes);

    vq_prep<<<4, 256>>>(embed);
    vq_main<<<N_BLOCKS, 256, smem_bytes>>>(inputs, embed, out);
    vq_finalize<<<1, 1024>>>(out);
}

// round 3
// speedup vs baseline: 1.8926x; 1.8926x over previous
#include <cuda_runtime.h>
#include <cuda_fp16.h>
#include <math.h>
#include <stdint.h>

#define K_CODES 1024
#define C_DIM   64
#define N_TOT   32768
#define TILE_N  128
#define CHUNK_K 128
#define N_CHUNKS 8
#define N_BLOCKS (N_TOT / TILE_N)   // 256

#define Q_ELEMS  (32*64*32*32)      // 2097152
#define LOSS_OFF Q_ELEMS
#define IDX_OFF  (Q_ELEMS + 1)
#define PERP_OFF (Q_ELEMS + 1 + N_TOT)

// smem byte offsets
#define OFF_ENRM  0          // 1024 floats  = 4096
#define OFF_SIDX  4096       // 128 ints     = 512
#define OFF_SRED  4608       // 8 floats
#define OFF_SXH   8192       // 128 rows x 144B (pitch 72 halfs)
#define OFF_SXL   (OFF_SXH + 18432)
#define OFF_SEH   (OFF_SXL + 18432)
#define OFF_SEL   (OFF_SEH + 18432)
#define SMEM_TOTAL (OFF_SEL + 18432)   // 81920 B -> 2 CTAs/SM
#define PITCH_B 144

// device scratch (no allocations allowed)
__device__ float  g_enrm[K_CODES];
__device__ int    g_counts[K_CODES];
__device__ float  g_loss_partial[N_BLOCKS];
__device__ __half g_eh[K_CODES * C_DIM];   // code-major [k][c]
__device__ __half g_el[K_CODES * C_DIM];

__device__ __forceinline__ uint32_t smem_u32(const void* p) {
    uint32_t a;
    asm("{ .reg .u64 t; cvta.to.shared.u64 t, %1; cvt.u32.u64 %0, t; }" : "=r"(a) : "l"(p));
    return a;
}
#define LDSM_X4(r0,r1,r2,r3,a) \
    asm volatile("ldmatrix.sync.aligned.m8n8.x4.shared.b16 {%0,%1,%2,%3}, [%4];" \
                 : "=r"(r0),"=r"(r1),"=r"(r2),"=r"(r3) : "r"(a))
#define MMA16816(c0,c1,c2,c3,a0,a1,a2,a3,b0,b1) \
    asm volatile("mma.sync.aligned.m16n8k16.row.col.f32.f16.f16.f32 " \
                 "{%0,%1,%2,%3}, {%4,%5,%6,%7}, {%8,%9}, {%0,%1,%2,%3};" \
                 : "+f"(c0),"+f"(c1),"+f"(c2),"+f"(c3) \
                 : "r"(a0),"r"(a1),"r"(a2),"r"(a3),"r"(b0),"r"(b1))

// ---------------------------------------------------------------------------
// Prep: fp16 hi/lo split of embed (code-major), ||e||^2, zero counts
// ---------------------------------------------------------------------------
__global__ void vq_prep(const float* __restrict__ embed) {
    int k = blockIdx.x * blockDim.x + threadIdx.x;   // 0..1023
    float s = 0.f;
#pragma unroll
    for (int c = 0; c < C_DIM; ++c) {
        float e = embed[c * K_CODES + k];
        s += e * e;
        __half h = __float2half_rn(e);
        __half l = __float2half_rn(e - __half2float(h));
        g_eh[k * C_DIM + c] = h;
        g_el[k * C_DIM + c] = l;
    }
    g_enrm[k]   = s;
    g_counts[k] = 0;
}

// ---------------------------------------------------------------------------
// Main: mma.sync fp16-split distance GEMM + fused argmin + gather + loss
// 8 warps x m16 rows = 128 vectors per CTA; codes in 8 chunks of 128.
// ---------------------------------------------------------------------------
__global__ __launch_bounds__(256, 2) void vq_main(const float* __restrict__ inputs,
                                                  const float* __restrict__ embed,
                                                  float* __restrict__ out)
{
    extern __shared__ __align__(128) char smem[];
    const uint32_t sb = smem_u32(smem);
    const int tid = threadIdx.x;
    const int wid = tid >> 5, lane = tid & 31;
    const int base_n = blockIdx.x * TILE_N;
    const int b = base_n >> 10, hw0 = base_n & 1023;

    float* senrm = (float*)(smem + OFF_ENRM);
    int*   sidx  = (int*)(smem + OFF_SIDX);
    float* sred  = (float*)(smem + OFF_SRED);

    // ||e||^2 table
    for (int i = tid; i < K_CODES; i += 256) senrm[i] = g_enrm[i];

    // x tile -> fp16 hi/lo planes, pitched rows (row = vector nl, 72 halfs)
    for (int idx = tid; idx < C_DIM * TILE_N; idx += 256) {
        int c = idx >> 7, nl = idx & 127;
        float x = inputs[b * 65536 + c * 1024 + hw0 + nl];
        __half xh = __float2half_rn(x);
        __half xl = __float2half_rn(x - __half2float(xh));
        *(__half*)(smem + OFF_SXH + nl * PITCH_B + c * 2) = xh;
        *(__half*)(smem + OFF_SXL + nl * PITCH_B + c * 2) = xl;
    }

    // A-fragment ldmatrix address for this thread (row-major m16k16 tiles)
    const uint32_t a_addr_h = sb + OFF_SXH + (wid * 16 + (lane & 15)) * PITCH_B
                            + (lane >> 4) * 16;
    const uint32_t a_addr_l = a_addr_h + (OFF_SXL - OFF_SXH);
    // B-fragment x4 address: 2 n-tiles per ldmatrix
    const int bm  = lane >> 3;             // 0..3
    const int bsub = lane & 7;
    const uint32_t b_row_off = (uint32_t)(((bm >> 1) * 8 + bsub) * PITCH_B + (bm & 1) * 16);

    float mind0 = 3.4e38f, mind1 = 3.4e38f;
    int   mini0 = 0,       mini1 = 0;

    for (int ck = 0; ck < N_CHUNKS; ++ck) {
        __syncthreads();
        // load e chunk (hi/lo) into pitched smem
        {
            const uint4* srch = (const uint4*)(g_eh + ck * CHUNK_K * C_DIM);
            const uint4* srcl = (const uint4*)(g_el + ck * CHUNK_K * C_DIM);
            for (int i = tid; i < 1024; i += 256) {       // 128 rows x 8 uint4
                int row = i >> 3, c16 = i & 7;
                uint32_t doff = (uint32_t)(row * PITCH_B + c16 * 16);
                *(uint4*)(smem + OFF_SEH + doff) = srch[i];
                *(uint4*)(smem + OFF_SEL + doff) = srcl[i];
            }
        }
        __syncthreads();

        float acc[16][4];
#pragma unroll
        for (int t = 0; t < 16; ++t)
#pragma unroll
            for (int q = 0; q < 4; ++q) acc[t][q] = 0.f;

#pragma unroll
        for (int ks = 0; ks < 4; ++ks) {
            uint32_t ah0, ah1, ah2, ah3, al0, al1, al2, al3;
            LDSM_X4(ah0, ah1, ah2, ah3, a_addr_h + ks * 32);
            LDSM_X4(al0, al1, al2, al3, a_addr_l + ks * 32);
#pragma unroll
            for (int nt = 0; nt < 16; nt += 2) {
                uint32_t bh0, bh1, bh2, bh3, bl0, bl1, bl2, bl3;
                uint32_t boff = (uint32_t)(nt * 8 * PITCH_B) + b_row_off + ks * 32;
                LDSM_X4(bh0, bh1, bh2, bh3, sb + OFF_SEH + boff);
                LDSM_X4(bl0, bl1, bl2, bl3, sb + OFF_SEL + boff);
                // 3 split terms: hh, hl, lh
                MMA16816(acc[nt][0],acc[nt][1],acc[nt][2],acc[nt][3],
                         ah0,ah1,ah2,ah3, bh0,bh1);
                MMA16816(acc[nt][0],acc[nt][1],acc[nt][2],acc[nt][3],
                         ah0,ah1,ah2,ah3, bl0,bl1);
                MMA16816(acc[nt][0],acc[nt][1],acc[nt][2],acc[nt][3],
                         al0,al1,al2,al3, bh0,bh1);
                MMA16816(acc[nt+1][0],acc[nt+1][1],acc[nt+1][2],acc[nt+1][3],
                         ah0,ah1,ah2,ah3, bh2,bh3);
                MMA16816(acc[nt+1][0],acc[nt+1][1],acc[nt+1][2],acc[nt+1][3],
                         ah0,ah1,ah2,ah3, bl2,bl3);
                MMA16816(acc[nt+1][0],acc[nt+1][1],acc[nt+1][2],acc[nt+1][3],
                         al0,al1,al2,al3, bh2,bh3);
            }
        }

        // fused argmin epilogue over this chunk's 128 codes
        const int k0 = ck * CHUNK_K;
#pragma unroll
        for (int nt = 0; nt < 16; ++nt) {
            int kc = k0 + nt * 8 + (lane & 3) * 2;
            float2 en = *(const float2*)(senrm + kc);
            float d0 = en.x - 2.f * acc[nt][0];
            float d1 = en.y - 2.f * acc[nt][1];
            float d2 = en.x - 2.f * acc[nt][2];
            float d3 = en.y - 2.f * acc[nt][3];
            if (d0 < mind0) { mind0 = d0; mini0 = kc; }
            if (d1 < mind0) { mind0 = d1; mini0 = kc + 1; }
            if (d2 < mind1) { mind1 = d2; mini1 = kc; }
            if (d3 < mind1) { mind1 = d3; mini1 = kc + 1; }
        }
    }

    // reduce across the 4 lanes sharing each fragment row (tie-break: low idx)
#pragma unroll
    for (int m = 1; m < 4; m <<= 1) {
        float od = __shfl_xor_sync(0xFFFFFFFFu, mind0, m);
        int   oi = __shfl_xor_sync(0xFFFFFFFFu, mini0, m);
        if (od < mind0 || (od == mind0 && oi < mini0)) { mind0 = od; mini0 = oi; }
        od = __shfl_xor_sync(0xFFFFFFFFu, mind1, m);
        oi = __shfl_xor_sync(0xFFFFFFFFu, mini1, m);
        if (od < mind1 || (od == mind1 && oi < mini1)) { mind1 = od; mini1 = oi; }
    }

    if ((lane & 3) == 0) {
        int r0 = wid * 16 + (lane >> 2);
        int r1 = r0 + 8;
        sidx[r0] = mini0;
        sidx[r1] = mini1;
        out[IDX_OFF + base_n + r0] = (float)mini0;
        out[IDX_OFF + base_n + r1] = (float)mini1;
        atomicAdd(&g_counts[mini0], 1);
        atomicAdd(&g_counts[mini1], 1);
    }
    __syncthreads();

    // gather quantized, write coalesced, loss partial (deterministic order)
    float lsum = 0.f;
    for (int idx = tid; idx < C_DIM * TILE_N; idx += 256) {
        int c = idx >> 7, nl = idx & 127;
        int kq = sidx[nl];
        float q = __ldg(&embed[c * 1024 + kq]);
        float x = inputs[b * 65536 + c * 1024 + hw0 + nl];
        out[b * 65536 + c * 1024 + hw0 + nl] = q;
        float dv = q - x;
        lsum += dv * dv;
    }
#pragma unroll
    for (int m = 16; m > 0; m >>= 1) lsum += __shfl_xor_sync(0xFFFFFFFFu, lsum, m);
    if (lane == 0) sred[wid] = lsum;
    __syncthreads();
    if (tid == 0) {
        float s = 0.f;
#pragma unroll
        for (int w = 0; w < 8; ++w) s += sred[w];
        g_loss_partial[blockIdx.x] = s;
    }
}

// ---------------------------------------------------------------------------
// Finalize: perplexity + loss (fixed-order trees)
// ---------------------------------------------------------------------------
__global__ void vq_finalize(float* __restrict__ out) {
    __shared__ float sh[1024];
    int t = threadIdx.x;

    float p = (float)g_counts[t] * (1.f / 32768.f);
    sh[t] = p * logf(p + 1e-10f);
    __syncthreads();
    for (int s = 512; s > 0; s >>= 1) {
        if (t < s) sh[t] += sh[t + s];
        __syncthreads();
    }
    if (t == 0) out[PERP_OFF] = expf(-sh[0]);
    __syncthreads();

    sh[t] = (t < N_BLOCKS) ? g_loss_partial[t] : 0.f;
    __syncthreads();
    for (int s = 512; s > 0; s >>= 1) {
        if (t < s) sh[t] += sh[t + s];
        __syncthreads();
    }
    if (t == 0) out[LOSS_OFF] = 0.25f * sh[0] / (float)Q_ELEMS;
}

// ---------------------------------------------------------------------------
extern "C" void kernel_launch(void* const* d_in, const int* in_sizes, int n_in,
                              void* d_out, int out_size) {
    const float* inputs = (const float*)d_in[0];
    const float* embed  = (const float*)d_in[1];
    if (n_in >= 2 && in_sizes[0] == K_CODES * C_DIM && in_sizes[1] == Q_ELEMS) {
        const float* t = inputs; inputs = embed; embed = t;
    }
    float* out = (float*)d_out;

    static int smem_set = 0;
    if (!smem_set) {
        cudaFuncSetAttribute(vq_main, cudaFuncAttributeMaxDynamicSharedMemorySize,
                             SMEM_TOTAL);
        smem_set = 1;
    }

    vq_prep<<<32, 32>>>(embed);
    vq_main<<<N_BLOCKS, 256, SMEM_TOTAL>>>(inputs, embed, out);
    vq_finalize<<<1, 1024>>>(out);
}

// round 5
// speedup vs baseline: 1.9573x; 1.0342x over previous
#include <cuda_runtime.h>
#include <cuda_fp16.h>
#include <math.h>
#include <stdint.h>

#define K_CODES 1024
#define C_DIM   64
#define N_TOT   32768
#define TILE_N  128
#define CHUNK_K 128
#define N_CHUNKS 8
#define N_BLOCKS (N_TOT / TILE_N)   // 256

#define Q_ELEMS  (32*64*32*32)      // 2097152
#define LOSS_OFF Q_ELEMS
#define IDX_OFF  (Q_ELEMS + 1)
#define PERP_OFF (Q_ELEMS + 1 + N_TOT)

#define PITCH_B   144               // 9 x 16B: conflict-free ldmatrix rows
#define PLANE_B   18432             // 128 rows x 144 B

// smem layout (dynamic)
#define OFF_SXH   0
#define OFF_SXL   (OFF_SXH + PLANE_B)
#define OFF_BH    (OFF_SXL + PLANE_B)        // buf stride 2*PLANE_B, l-plane +PLANE_B
#define BUF_STRIDE (2 * PLANE_B)
#define OFF_ENRM  (OFF_BH + 2 * BUF_STRIDE)  // 2 bufs x 512 B
#define OFF_SIDX  (OFF_ENRM + 1024)          // 128 ints
#define OFF_SRED  (OFF_SIDX + 512)           // 8 floats + flag
#define OFF_SCR   (OFF_ENRM)                 // finalize scratch reuses enrm (256 f)
#define SMEM_TOTAL (OFF_SRED + 64)           // 112192 B -> 2 CTAs/SM

// device scratch (no allocations allowed)
__device__ float  g_enrm[K_CODES];
__device__ int    g_counts[K_CODES];
__device__ float  g_loss_partial[N_BLOCKS];
__device__ int    g_ticket;
__device__ __half g_eh[K_CODES * C_DIM];   // code-major [k][c]
__device__ __half g_el[K_CODES * C_DIM];

__device__ __forceinline__ uint32_t smem_u32(const void* p) {
    uint32_t a;
    asm("{ .reg .u64 t; cvta.to.shared.u64 t, %1; cvt.u32.u64 %0, t; }" : "=r"(a) : "l"(p));
    return a;
}
__device__ __forceinline__ void cp16(uint32_t dst, const void* src) {
    asm volatile("cp.async.cg.shared.global [%0], [%1], 16;" :: "r"(dst), "l"(src));
}
#define CP_COMMIT() asm volatile("cp.async.commit_group;" ::: "memory")
#define CP_WAIT(n)  asm volatile("cp.async.wait_group %0;" :: "n"(n) : "memory")

#define LDSM_X4(r0,r1,r2,r3,a) \
    asm volatile("ldmatrix.sync.aligned.m8n8.x4.shared.b16 {%0,%1,%2,%3}, [%4];" \
                 : "=r"(r0),"=r"(r1),"=r"(r2),"=r"(r3) : "r"(a))
#define MMA16816(c0,c1,c2,c3,a0,a1,a2,a3,b0,b1) \
    asm volatile("mma.sync.aligned.m16n8k16.row.col.f32.f16.f16.f32 " \
                 "{%0,%1,%2,%3}, {%4,%5,%6,%7}, {%8,%9}, {%0,%1,%2,%3};" \
                 : "+f"(c0),"+f"(c1),"+f"(c2),"+f"(c3) \
                 : "r"(a0),"r"(a1),"r"(a2),"r"(a3),"r"(b0),"r"(b1))

// ---------------------------------------------------------------------------
// Prep: smem-tiled transpose of embed -> fp16 hi/lo (code-major), ||e||^2,
// zero counts, reset ticket.  16 blocks x 256 threads.
// ---------------------------------------------------------------------------
__global__ __launch_bounds__(256) void vq_prep(const float* __restrict__ embed) {
    __shared__ float tile[64][65];
    __shared__ float nred[4][64];
    const int tid = threadIdx.x;
    const int k0 = blockIdx.x * 64;

    for (int i = tid; i < 4096; i += 256) {       // coalesced 64-float rows
        int c = i >> 6, kk = i & 63;
        tile[c][kk] = embed[c * K_CODES + k0 + kk];
    }
    __syncthreads();

    const int kk = tid & 63, part = tid >> 6;     // part: 16-c slice
    float s = 0.f;
    uint32_t hw[8], lw[8];
#pragma unroll
    for (int j = 0; j < 8; ++j) {
        int c0 = part * 16 + j * 2;
        float e0 = tile[c0][kk], e1 = tile[c0 + 1][kk];
        s += e0 * e0 + e1 * e1;
        __half h0 = __float2half_rn(e0), h1 = __float2half_rn(e1);
        __half l0 = __float2half_rn(e0 - __half2float(h0));
        __half l1 = __float2half_rn(e1 - __half2float(h1));
        hw[j] = (uint32_t)__half_as_ushort(h0) | ((uint32_t)__half_as_ushort(h1) << 16);
        lw[j] = (uint32_t)__half_as_ushort(l0) | ((uint32_t)__half_as_ushort(l1) << 16);
    }
    {
        uint4* dh = (uint4*)&g_eh[(k0 + kk) * C_DIM + part * 16];
        uint4* dl = (uint4*)&g_el[(k0 + kk) * C_DIM + part * 16];
        dh[0] = make_uint4(hw[0], hw[1], hw[2], hw[3]);
        dh[1] = make_uint4(hw[4], hw[5], hw[6], hw[7]);
        dl[0] = make_uint4(lw[0], lw[1], lw[2], lw[3]);
        dl[1] = make_uint4(lw[4], lw[5], lw[6], lw[7]);
    }
    nred[part][kk] = s;
    __syncthreads();
    if (part == 0) {
        g_enrm[k0 + kk] = nred[0][kk] + nred[1][kk] + nred[2][kk] + nred[3][kk];
        g_counts[k0 + kk] = 0;
    }
    if (blockIdx.x == 0 && tid == 0) g_ticket = 0;
}

// ---------------------------------------------------------------------------
// Main: mma.sync fp16-split distance GEMM, cp.async double-buffered B,
// fused argmin + gather + loss; last CTA finalizes loss/perplexity.
// ---------------------------------------------------------------------------
__device__ __forceinline__ void load_chunk(int ck, int buf, uint32_t sb, int tid) {
    const __half* srch = g_eh + ck * CHUNK_K * C_DIM;
    const __half* srcl = g_el + ck * CHUNK_K * C_DIM;
    const uint32_t dbase = sb + OFF_BH + buf * BUF_STRIDE;
#pragma unroll
    for (int p = 0; p < 4; ++p) {
        int i = tid + p * 256;                  // granule id 0..1023
        int r = i >> 3, g = i & 7;
        uint32_t doff = (uint32_t)(r * PITCH_B + g * 16);
        cp16(dbase + doff,           srch + i * 8);
        cp16(dbase + PLANE_B + doff, srcl + i * 8);
    }
    if (tid < 32)
        cp16(sb + OFF_ENRM + buf * 512 + tid * 16, g_enrm + ck * CHUNK_K + tid * 4);
    CP_COMMIT();
}

__global__ __launch_bounds__(256, 2) void vq_main(const float* __restrict__ inputs,
                                                  const float* __restrict__ embed,
                                                  float* __restrict__ out)
{
    extern __shared__ __align__(128) char smem[];
    const uint32_t sb = smem_u32(smem);
    const int tid = threadIdx.x;
    const int wid = tid >> 5, lane = tid & 31;
    const int base_n = blockIdx.x * TILE_N;
    const int b = base_n >> 10, hw0 = base_n & 1023;

    int*   sidx = (int*)(smem + OFF_SIDX);
    float* sred = (float*)(smem + OFF_SRED);

    // pipeline: chunks 0 and 1 in flight immediately
    load_chunk(0, 0, sb, tid);
    load_chunk(1, 1, sb, tid);

    // x tile -> fp16 hi/lo planes, pitched rows (row = vector nl)
    for (int idx = tid; idx < C_DIM * TILE_N; idx += 256) {
        int c = idx >> 7, nl = idx & 127;
        float x = inputs[b * 65536 + c * 1024 + hw0 + nl];
        __half xh = __float2half_rn(x);
        __half xl = __float2half_rn(x - __half2float(xh));
        *(__half*)(smem + OFF_SXH + nl * PITCH_B + c * 2) = xh;
        *(__half*)(smem + OFF_SXL + nl * PITCH_B + c * 2) = xl;
    }

    const uint32_t a_addr_h = sb + OFF_SXH + (wid * 16 + (lane & 15)) * PITCH_B
                            + (lane >> 4) * 16;
    const uint32_t a_addr_l = a_addr_h + (OFF_SXL - OFF_SXH);
    const int bm = lane >> 3, bsub = lane & 7;
    const uint32_t b_row_off = (uint32_t)(((bm >> 1) * 8 + bsub) * PITCH_B + (bm & 1) * 16);

    float mind0 = 3.4e38f, mind1 = 3.4e38f;
    int   mini0 = 0,       mini1 = 0;

    for (int ck = 0; ck < N_CHUNKS; ++ck) {
        const int buf = ck & 1;
        if (ck == N_CHUNKS - 1) CP_WAIT(0); else CP_WAIT(1);
        __syncthreads();

        float acc[16][4];
#pragma unroll
        for (int t = 0; t < 16; ++t)
#pragma unroll
            for (int q = 0; q < 4; ++q) acc[t][q] = 0.f;

        const uint32_t bh_base = sb + OFF_BH + buf * BUF_STRIDE;
#pragma unroll
        for (int ks = 0; ks < 4; ++ks) {
            uint32_t ah0, ah1, ah2, ah3, al0, al1, al2, al3;
            LDSM_X4(ah0, ah1, ah2, ah3, a_addr_h + ks * 32);
            LDSM_X4(al0, al1, al2, al3, a_addr_l + ks * 32);
#pragma unroll
            for (int nt = 0; nt < 16; nt += 2) {
                uint32_t bh0, bh1, bh2, bh3, bl0, bl1, bl2, bl3;
                uint32_t boff = (uint32_t)(nt * 8 * PITCH_B) + b_row_off + ks * 32;
                LDSM_X4(bh0, bh1, bh2, bh3, bh_base + boff);
                LDSM_X4(bl0, bl1, bl2, bl3, bh_base + PLANE_B + boff);
                // interleaved 3-term chains (hh, hl, lh) across the 2 n-tiles
                MMA16816(acc[nt][0],acc[nt][1],acc[nt][2],acc[nt][3],
                         ah0,ah1,ah2,ah3, bh0,bh1);
                MMA16816(acc[nt+1][0],acc[nt+1][1],acc[nt+1][2],acc[nt+1][3],
                         ah0,ah1,ah2,ah3, bh2,bh3);
                MMA16816(acc[nt][0],acc[nt][1],acc[nt][2],acc[nt][3],
                         ah0,ah1,ah2,ah3, bl0,bl1);
                MMA16816(acc[nt+1][0],acc[nt+1][1],acc[nt+1][2],acc[nt+1][3],
                         ah0,ah1,ah2,ah3, bl2,bl3);
                MMA16816(acc[nt][0],acc[nt][1],acc[nt][2],acc[nt][3],
                         al0,al1,al2,al3, bh0,bh1);
                MMA16816(acc[nt+1][0],acc[nt+1][1],acc[nt+1][2],acc[nt+1][3],
                         al0,al1,al2,al3, bh2,bh3);
            }
        }

        // fused argmin over this chunk's 128 codes (chunk-local enrm buffer)
        const float* senrm = (const float*)(smem + OFF_ENRM + buf * 512);
        const int k0c = ck * CHUNK_K;
#pragma unroll
        for (int nt = 0; nt < 16; ++nt) {
            int kl = nt * 8 + (lane & 3) * 2;
            float2 en = *(const float2*)(senrm + kl);
            float d0 = en.x - 2.f * acc[nt][0];
            float d1 = en.y - 2.f * acc[nt][1];
            float d2 = en.x - 2.f * acc[nt][2];
            float d3 = en.y - 2.f * acc[nt][3];
            int kc = k0c + kl;
            if (d0 < mind0) { mind0 = d0; mini0 = kc; }
            if (d1 < mind0) { mind0 = d1; mini0 = kc + 1; }
            if (d2 < mind1) { mind1 = d2; mini1 = kc; }
            if (d3 < mind1) { mind1 = d3; mini1 = kc + 1; }
        }
        __syncthreads();
        if (ck + 2 < N_CHUNKS) load_chunk(ck + 2, buf, sb, tid);
    }

    // reduce across the 4 lanes sharing each fragment row (tie-break: low idx)
#pragma unroll
    for (int m = 1; m < 4; m <<= 1) {
        float od = __shfl_xor_sync(0xFFFFFFFFu, mind0, m);
        int   oi = __shfl_xor_sync(0xFFFFFFFFu, mini0, m);
        if (od < mind0 || (od == mind0 && oi < mini0)) { mind0 = od; mini0 = oi; }
        od = __shfl_xor_sync(0xFFFFFFFFu, mind1, m);
        oi = __shfl_xor_sync(0xFFFFFFFFu, mini1, m);
        if (od < mind1 || (od == mind1 && oi < mini1)) { mind1 = od; mini1 = oi; }
    }

    if ((lane & 3) == 0) {
        int r0 = wid * 16 + (lane >> 2);
        int r1 = r0 + 8;
        sidx[r0] = mini0;
        sidx[r1] = mini1;
        out[IDX_OFF + base_n + r0] = (float)mini0;
        out[IDX_OFF + base_n + r1] = (float)mini1;
        atomicAdd(&g_counts[mini0], 1);
        atomicAdd(&g_counts[mini1], 1);
    }
    __syncthreads();

    // gather quantized, write coalesced, loss partial (deterministic order)
    float lsum = 0.f;
    for (int idx = tid; idx < C_DIM * TILE_N; idx += 256) {
        int c = idx >> 7, nl = idx & 127;
        int kq = sidx[nl];
        float q = __ldg(&embed[c * 1024 + kq]);
        float x = inputs[b * 65536 + c * 1024 + hw0 + nl];
        out[b * 65536 + c * 1024 + hw0 + nl] = q;
        float dv = q - x;
        lsum += dv * dv;
    }
#pragma unroll
    for (int m = 16; m > 0; m >>= 1) lsum += __shfl_xor_sync(0xFFFFFFFFu, lsum, m);
    if (lane == 0) sred[wid] = lsum;
    __syncthreads();
    if (tid == 0) {
        float s = 0.f;
#pragma unroll
        for (int w = 0; w < 8; ++w) s += sred[w];
        g_loss_partial[blockIdx.x] = s;
    }

    // ---- last-CTA finalize (loss + perplexity), deterministic trees ----
    __threadfence();
    __syncthreads();
    int* flag = (int*)(smem + OFF_SRED + 32);
    if (tid == 0) {
        int old = atomicAdd(&g_ticket, 1);
        *flag = (old == N_BLOCKS - 1);
    }
    __syncthreads();
    if (*flag) {
        __threadfence();
        float* scr = (float*)(smem + OFF_SCR);
        float ps = 0.f;
#pragma unroll
        for (int j = 0; j < 4; ++j) {
            int k = tid + j * 256;
            float p = (float)g_counts[k] * (1.f / 32768.f);
            ps += p * logf(p + 1e-10f);
        }
        scr[tid] = ps;
        __syncthreads();
        for (int s = 128; s > 0; s >>= 1) {
            if (tid < s) scr[tid] += scr[tid + s];
            __syncthreads();
        }
        if (tid == 0) out[PERP_OFF] = expf(-scr[0]);
        __syncthreads();
        scr[tid] = g_loss_partial[tid];
        __syncthreads();
        for (int s = 128; s > 0; s >>= 1) {
            if (tid < s) scr[tid] += scr[tid + s];
            __syncthreads();
        }
        if (tid == 0) out[LOSS_OFF] = 0.25f * scr[0] / (float)Q_ELEMS;
    }
}

// ---------------------------------------------------------------------------
extern "C" void kernel_launch(void* const* d_in, const int* in_sizes, int n_in,
                              void* d_out, int out_size) {
    const float* inputs = (const float*)d_in[0];
    const float* embed  = (const float*)d_in[1];
    if (n_in >= 2 && in_sizes[0] == K_CODES * C_DIM && in_sizes[1] == Q_ELEMS) {
        const float* t = inputs; inputs = embed; embed = t;
    }
    float* out = (float*)d_out;

    static int smem_set = 0;
    if (!smem_set) {
        cudaFuncSetAttribute(vq_main, cudaFuncAttributeMaxDynamicSharedMemorySize,
                             SMEM_TOTAL);
        smem_set = 1;
    }

    vq_prep<<<16, 256>>>(embed);
    vq_main<<<N_BLOCKS, 256, SMEM_TOTAL>>>(inputs, embed, out);
}